// round 3
// baseline (speedup 1.0000x reference)
#include <cuda_runtime.h>

// ---------------------------------------------------------------------------
// GCN 2-layer forward, pull-based CSR gather with deferred normalization:
//   xt  = x@W                                   (GEMM, no scale -> CSR-indep)
//   out[d] = ( dinv[d]*xt[d] + sum_e dinv[s]*xt[s] ) * dinv[d] + b   (+relu)
// CSR build (stream s2) runs concurrently with GEMM1 (stream 0).
// ---------------------------------------------------------------------------

#define NODES_MAX 100000
#define EDGES_MAX 1600000
#define FEAT_IN   128
#define FEAT      64

__device__ float g_y   [(size_t)NODES_MAX * FEAT];   // xt buffer (both layers)
__device__ float g_h   [(size_t)NODES_MAX * FEAT];   // layer-1 activations
__device__ float g_dinv[NODES_MAX];
__device__ int   g_deg [NODES_MAX];
__device__ int   g_off [NODES_MAX + 1];
__device__ int   g_cur [NODES_MAX];
__device__ int   g_csr [EDGES_MAX];
__device__ int   g_bsum[256];

// ---------------------------------------------------------------------------
// Per-warp inline dtype detection: int64 indices (<2^31) have all-zero odd
// int32 words; genuine int32 node-ids make that probability ~(1e-5)^32.
// ---------------------------------------------------------------------------
__device__ __forceinline__ int detect64(const int* __restrict__ ei) {
    int lane = threadIdx.x & 31;
    int v = __ldg(&ei[2 * lane + 1]);
    return (__ballot_sync(0xffffffffu, v != 0) == 0u) ? 1 : 0;
}

__global__ void deg_count_kernel(const int* __restrict__ ei, int* __restrict__ deg, int E) {
    int is64 = detect64(ei);
    int e = blockIdx.x * blockDim.x + threadIdx.x;
    if (e >= E) return;
    long long pos = (long long)E + e;           // dst row
    int d = is64 ? ei[2 * pos] : ei[pos];
    atomicAdd(&deg[d], 1);
}

// ---------------------------------------------------------------------------
// Block-wide exclusive scan (blockDim multiple of 32, <=1024).
// ---------------------------------------------------------------------------
__device__ __forceinline__ int block_exscan(int v, int* total) {
    __shared__ int wsum[32];
    int lane = threadIdx.x & 31, wid = threadIdx.x >> 5;
    int nw = blockDim.x >> 5;
    int inc = v;
#pragma unroll
    for (int o = 1; o < 32; o <<= 1) {
        int t = __shfl_up_sync(0xffffffffu, inc, o);
        if (lane >= o) inc += t;
    }
    if (lane == 31) wsum[wid] = inc;
    __syncthreads();
    if (wid == 0) {
        int ws = (lane < nw) ? wsum[lane] : 0;
#pragma unroll
        for (int o = 1; o < 32; o <<= 1) {
            int t = __shfl_up_sync(0xffffffffu, ws, o);
            if (lane >= o) ws += t;
        }
        wsum[lane] = ws;
    }
    __syncthreads();
    int woff = (wid == 0) ? 0 : wsum[wid - 1];
    *total = wsum[nw - 1];
    return woff + inc - v;
}

// scanA: per-block local exclusive scan of deg -> off, block totals -> bsum.
__global__ __launch_bounds__(1024) void scanA_kernel(
    const int* __restrict__ deg, int* __restrict__ off,
    int* __restrict__ bsum, int n)
{
    int i = blockIdx.x * blockDim.x + threadIdx.x;
    int v = (i < n) ? deg[i] : 0;
    int tot;
    int ex = block_exscan(v, &tot);
    if (i < n) off[i] = ex;
    if (threadIdx.x == 0) bsum[blockIdx.x] = tot;
}

// scanB: add block prefix (each block reduces bsum[0..b) itself), finalize
// off/cur and compute dinv in the same pass.
__global__ __launch_bounds__(1024) void scanB_kernel(
    const int* __restrict__ deg, int* __restrict__ off,
    const int* __restrict__ bsum, int* __restrict__ cur,
    float* __restrict__ dinv, int n, int nb, int E)
{
    __shared__ int sb[128];
    int t = threadIdx.x, b = blockIdx.x;
    if (t < 128) sb[t] = (t < nb && t < b) ? bsum[t] : 0;
    __syncthreads();
#pragma unroll
    for (int o = 64; o > 0; o >>= 1) {
        if (t < o) sb[t] += sb[t + o];
        __syncthreads();
    }
    int pre = sb[0];
    int i = b * blockDim.x + t;
    if (i < n) {
        int o = off[i] + pre;
        off[i] = o;
        cur[i] = o;
        dinv[i] = rsqrtf((float)(deg[i] + 1));  // +1 self-loop
    }
    if (b == 0 && t == 0) off[n] = E;
}

__global__ void fill_kernel(const int* __restrict__ ei, int* __restrict__ cur,
                            int* __restrict__ csr, int E) {
    int is64 = detect64(ei);
    int e = blockIdx.x * blockDim.x + threadIdx.x;
    if (e >= E) return;
    int s, d;
    if (is64) {
        s = ei[2 * (long long)e];
        d = ei[2 * ((long long)E + e)];
    } else {
        s = ei[e];
        d = ei[(long long)E + e];
    }
    int pos = atomicAdd(&cur[d], 1);
    csr[pos] = s;
}

// ---------------------------------------------------------------------------
// Tiled GEMM (no scaling): xt[i][c] = sum_k X[i][k] W[k][c]
// ---------------------------------------------------------------------------
template <int K>
__global__ __launch_bounds__(256) void gemm_kernel(
    const float* __restrict__ X, const float* __restrict__ W,
    float* __restrict__ y, int n)
{
    constexpr int BN = 128;
    constexpr int KC = 32;
    __shared__ __align__(16) float Xs[BN][KC];
    __shared__ __align__(16) float Ws[KC][64];

    int tid = threadIdx.x;
    int cg  = tid & 15;
    int ng  = tid >> 4;
    int node0 = blockIdx.x * BN;

    float4 accv[8];
#pragma unroll
    for (int i = 0; i < 8; i++) accv[i] = make_float4(0.f, 0.f, 0.f, 0.f);

    for (int kc = 0; kc < K; kc += KC) {
#pragma unroll
        for (int l = 0; l < 4; l++) {
            int fi = tid + l * 256;
            int r  = fi >> 3;
            int c  = (fi & 7) << 2;
            int node = node0 + r;
            float4 v = make_float4(0.f, 0.f, 0.f, 0.f);
            if (node < n) v = *(const float4*)(X + (size_t)node * K + kc + c);
            *(float4*)(&Xs[r][c]) = v;
        }
#pragma unroll
        for (int l = 0; l < 2; l++) {
            int fi = tid + l * 256;
            int r  = fi >> 4;
            int c  = (fi & 15) << 2;
            *(float4*)(&Ws[r][c]) = *(const float4*)(W + (size_t)(kc + r) * 64 + c);
        }
        __syncthreads();

#pragma unroll
        for (int k4 = 0; k4 < KC; k4 += 4) {
            float4 wr[4];
#pragma unroll
            for (int kk = 0; kk < 4; kk++)
                wr[kk] = *(float4*)(&Ws[k4 + kk][cg << 2]);
#pragma unroll
            for (int i = 0; i < 8; i++) {
                float4 xq = *(float4*)(&Xs[ng + 16 * i][k4]);
                accv[i].x = fmaf(xq.x, wr[0].x, accv[i].x);
                accv[i].y = fmaf(xq.x, wr[0].y, accv[i].y);
                accv[i].z = fmaf(xq.x, wr[0].z, accv[i].z);
                accv[i].w = fmaf(xq.x, wr[0].w, accv[i].w);
                accv[i].x = fmaf(xq.y, wr[1].x, accv[i].x);
                accv[i].y = fmaf(xq.y, wr[1].y, accv[i].y);
                accv[i].z = fmaf(xq.y, wr[1].z, accv[i].z);
                accv[i].w = fmaf(xq.y, wr[1].w, accv[i].w);
                accv[i].x = fmaf(xq.z, wr[2].x, accv[i].x);
                accv[i].y = fmaf(xq.z, wr[2].y, accv[i].y);
                accv[i].z = fmaf(xq.z, wr[2].z, accv[i].z);
                accv[i].w = fmaf(xq.z, wr[2].w, accv[i].w);
                accv[i].x = fmaf(xq.w, wr[3].x, accv[i].x);
                accv[i].y = fmaf(xq.w, wr[3].y, accv[i].y);
                accv[i].z = fmaf(xq.w, wr[3].z, accv[i].z);
                accv[i].w = fmaf(xq.w, wr[3].w, accv[i].w);
            }
        }
        __syncthreads();
    }

#pragma unroll
    for (int i = 0; i < 8; i++) {
        int node = node0 + ng + 16 * i;
        if (node < n)
            *(float4*)(y + (size_t)node * 64 + (cg << 2)) = accv[i];
    }
}

// ---------------------------------------------------------------------------
// Fused gather + norm + epilogue. ONE WARP PER NODE (no intra-warp pairing
// imbalance): lane owns float2 of the 64-wide row. Edge loop unrolled x4.
// out[d] = (relu)( dinv[d]*( dinv[d]*xt[d] + sum dinv[s]*xt[s] ) + b )
// ---------------------------------------------------------------------------
template <bool RELU>
__global__ __launch_bounds__(256) void gather_kernel(
    const int* __restrict__ off, const int* __restrict__ csr,
    const float2* __restrict__ xt, const float* __restrict__ dinv,
    const float2* __restrict__ b, float2* __restrict__ out, int n)
{
    int warp = (blockIdx.x * blockDim.x + threadIdx.x) >> 5;
    int lane = threadIdx.x & 31;
    if (warp >= n) return;
    int node = warp;

    int j   = off[node];
    int end = off[node + 1];
    float dd = dinv[node];

    float2 a = xt[(size_t)node * 32 + lane];
    float2 acc;
    acc.x = dd * a.x;
    acc.y = dd * a.y;

    for (; j + 4 <= end; j += 4) {
        int s0 = csr[j], s1 = csr[j + 1], s2 = csr[j + 2], s3 = csr[j + 3];
        float d0 = dinv[s0], d1 = dinv[s1], d2 = dinv[s2], d3 = dinv[s3];
        float2 v0 = xt[(size_t)s0 * 32 + lane];
        float2 v1 = xt[(size_t)s1 * 32 + lane];
        float2 v2 = xt[(size_t)s2 * 32 + lane];
        float2 v3 = xt[(size_t)s3 * 32 + lane];
        acc.x = fmaf(d0, v0.x, acc.x);
        acc.y = fmaf(d0, v0.y, acc.y);
        acc.x = fmaf(d1, v1.x, acc.x);
        acc.y = fmaf(d1, v1.y, acc.y);
        acc.x = fmaf(d2, v2.x, acc.x);
        acc.y = fmaf(d2, v2.y, acc.y);
        acc.x = fmaf(d3, v3.x, acc.x);
        acc.y = fmaf(d3, v3.y, acc.y);
    }
    for (; j < end; j++) {
        int s0 = csr[j];
        float d0 = dinv[s0];
        float2 v0 = xt[(size_t)s0 * 32 + lane];
        acc.x = fmaf(d0, v0.x, acc.x);
        acc.y = fmaf(d0, v0.y, acc.y);
    }

    float2 bb = b[lane];
    float2 r;
    r.x = fmaf(acc.x, dd, bb.x);
    r.y = fmaf(acc.y, dd, bb.y);
    if (RELU) {
        r.x = fmaxf(r.x, 0.f);
        r.y = fmaxf(r.y, 0.f);
    }
    out[(size_t)node * 32 + lane] = r;
}

// ---------------------------------------------------------------------------
extern "C" void kernel_launch(void* const* d_in, const int* in_sizes, int n_in,
                              void* d_out, int out_size)
{
    const float* x  = (const float*)d_in[0];
    const int*   ei = (const int*)d_in[1];
    const float* W1 = (const float*)d_in[2];
    const float* b1 = (const float*)d_in[3];
    const float* W2 = (const float*)d_in[4];
    const float* b2 = (const float*)d_in[5];

    int n = in_sizes[0] / FEAT_IN;   // 100000
    int E = in_sizes[1] / 2;         // 1600000

    float *y, *h, *dinv;
    int *deg, *off, *cur, *csr, *bsum;
    cudaGetSymbolAddress((void**)&y,    g_y);
    cudaGetSymbolAddress((void**)&h,    g_h);
    cudaGetSymbolAddress((void**)&dinv, g_dinv);
    cudaGetSymbolAddress((void**)&deg,  g_deg);
    cudaGetSymbolAddress((void**)&off,  g_off);
    cudaGetSymbolAddress((void**)&cur,  g_cur);
    cudaGetSymbolAddress((void**)&csr,  g_csr);
    cudaGetSymbolAddress((void**)&bsum, g_bsum);

    // Side stream + events, created once on the first (uncaptured) call.
    static cudaStream_t s2 = nullptr;
    static cudaEvent_t evFork = nullptr, evJoin = nullptr;
    if (s2 == nullptr) {
        cudaStreamCreateWithFlags(&s2, cudaStreamNonBlocking);
        cudaEventCreateWithFlags(&evFork, cudaEventDisableTiming);
        cudaEventCreateWithFlags(&evJoin, cudaEventDisableTiming);
    }

    const int T = 256;
    int eb = (E + T - 1) / T;
    int nbs = (n + 1023) / 1024;            // scan blocks (98)
    int gb = (n * 32 + T - 1) / T;          // gather blocks (1 warp/node)

    // ---- Fork: CSR build on s2, GEMM1 on main stream ----
    cudaEventRecord(evFork, 0);
    cudaStreamWaitEvent(s2, evFork, 0);

    cudaMemsetAsync(deg, 0, (size_t)n * sizeof(int), s2);
    deg_count_kernel<<<eb, T, 0, s2>>>(ei, deg, E);
    scanA_kernel<<<nbs, 1024, 0, s2>>>(deg, off, bsum, n);
    scanB_kernel<<<nbs, 1024, 0, s2>>>(deg, off, bsum, cur, dinv, n, nbs, E);
    fill_kernel<<<eb, T, 0, s2>>>(ei, cur, csr, E);
    cudaEventRecord(evJoin, s2);

    gemm_kernel<128><<<(n + 127) / 128, 256>>>(x, W1, y, n);   // stream 0, concurrent

    // ---- Join ----
    cudaStreamWaitEvent(0, evJoin, 0);

    gather_kernel<true><<<gb, T>>>(off, csr, (const float2*)y, dinv,
                                   (const float2*)b1, (float2*)h, n);

    gemm_kernel<64><<<(n + 127) / 128, 256>>>(h, W2, y, n);
    gather_kernel<false><<<gb, T>>>(off, csr, (const float2*)y, dinv,
                                    (const float2*)b2, (float2*)d_out, n);
}

// round 4
// speedup vs baseline: 1.0841x; 1.0841x over previous
#include <cuda_runtime.h>

// ---------------------------------------------------------------------------
// GCN 2-layer forward, pull-based CSR gather:
//   y   = (x@W) * dinv[:,None]                       (GEMM + row scale)
//   out[d] = ( y[d] + sum_{e:dst=d} y[src_e] ) * dinv[d] + b   (+relu L1)
// Main stream: deg -> dinv -> GEMM1 -> (join) -> gather1 -> GEMM2 -> gather2
// Side stream: scanA -> scanB -> fill   (overlaps GEMM1)
// ---------------------------------------------------------------------------

#define NODES_MAX 100000
#define EDGES_MAX 1600000
#define FEAT_IN   128
#define FEAT      64

__device__ float g_y   [(size_t)NODES_MAX * FEAT];
__device__ float g_h   [(size_t)NODES_MAX * FEAT];
__device__ float g_dinv[NODES_MAX];
__device__ int   g_deg [NODES_MAX];
__device__ int   g_off [NODES_MAX + 1];
__device__ int   g_cur [NODES_MAX];
__device__ int   g_csr [EDGES_MAX];
__device__ int   g_bsum[256];

// ---------------------------------------------------------------------------
// Per-warp inline dtype detection: int64 indices (<2^31) have all-zero odd
// int32 words.
// ---------------------------------------------------------------------------
__device__ __forceinline__ int detect64(const int* __restrict__ ei) {
    int lane = threadIdx.x & 31;
    int v = __ldg(&ei[2 * lane + 1]);
    return (__ballot_sync(0xffffffffu, v != 0) == 0u) ? 1 : 0;
}

__global__ void zero_deg_kernel(int* __restrict__ deg, int n) {
    int i = blockIdx.x * blockDim.x + threadIdx.x;
    if (i < n) deg[i] = 0;
}

// 4 edges per thread, vectorized index loads.
__global__ void deg_count_kernel(const int* __restrict__ ei, int* __restrict__ deg, int E) {
    int is64 = detect64(ei);
    int e0 = 4 * (blockIdx.x * blockDim.x + threadIdx.x);
    if (e0 >= E) return;
    if (e0 + 4 <= E) {
        if (is64) {
            const longlong2* p = (const longlong2*)ei + E / 2 + e0 / 2;  // dst row base
            longlong2 a = p[0], b = p[1];
            atomicAdd(&deg[(int)a.x], 1);
            atomicAdd(&deg[(int)a.y], 1);
            atomicAdd(&deg[(int)b.x], 1);
            atomicAdd(&deg[(int)b.y], 1);
        } else {
            int4 d4 = *(const int4*)(ei + E + e0);
            atomicAdd(&deg[d4.x], 1);
            atomicAdd(&deg[d4.y], 1);
            atomicAdd(&deg[d4.z], 1);
            atomicAdd(&deg[d4.w], 1);
        }
    } else {
        for (int e = e0; e < E; e++) {
            long long pos = (long long)E + e;
            int d = is64 ? ei[2 * pos] : ei[pos];
            atomicAdd(&deg[d], 1);
        }
    }
}

__global__ void dinv_kernel(const int* __restrict__ deg, float* __restrict__ dinv, int n) {
    int i = blockIdx.x * blockDim.x + threadIdx.x;
    if (i < n) dinv[i] = rsqrtf((float)(deg[i] + 1));  // +1 self-loop
}

// ---------------------------------------------------------------------------
// Block-wide exclusive scan (blockDim multiple of 32, <=1024).
// ---------------------------------------------------------------------------
__device__ __forceinline__ int block_exscan(int v, int* total) {
    __shared__ int wsum[32];
    int lane = threadIdx.x & 31, wid = threadIdx.x >> 5;
    int nw = blockDim.x >> 5;
    int inc = v;
#pragma unroll
    for (int o = 1; o < 32; o <<= 1) {
        int t = __shfl_up_sync(0xffffffffu, inc, o);
        if (lane >= o) inc += t;
    }
    if (lane == 31) wsum[wid] = inc;
    __syncthreads();
    if (wid == 0) {
        int ws = (lane < nw) ? wsum[lane] : 0;
#pragma unroll
        for (int o = 1; o < 32; o <<= 1) {
            int t = __shfl_up_sync(0xffffffffu, ws, o);
            if (lane >= o) ws += t;
        }
        wsum[lane] = ws;
    }
    __syncthreads();
    int woff = (wid == 0) ? 0 : wsum[wid - 1];
    *total = wsum[nw - 1];
    return woff + inc - v;
}

__global__ __launch_bounds__(1024) void scanA_kernel(
    const int* __restrict__ deg, int* __restrict__ off,
    int* __restrict__ bsum, int n)
{
    int i = blockIdx.x * blockDim.x + threadIdx.x;
    int v = (i < n) ? deg[i] : 0;
    int tot;
    int ex = block_exscan(v, &tot);
    if (i < n) off[i] = ex;
    if (threadIdx.x == 0) bsum[blockIdx.x] = tot;
}

__global__ __launch_bounds__(1024) void scanB_kernel(
    int* __restrict__ off, const int* __restrict__ bsum,
    int* __restrict__ cur, int n, int nb, int E)
{
    __shared__ int sb[128];
    int t = threadIdx.x, b = blockIdx.x;
    if (t < 128) sb[t] = (t < nb && t < b) ? bsum[t] : 0;
    __syncthreads();
#pragma unroll
    for (int o = 64; o > 0; o >>= 1) {
        if (t < o) sb[t] += sb[t + o];
        __syncthreads();
    }
    int pre = sb[0];
    int i = b * blockDim.x + t;
    if (i < n) {
        int o = off[i] + pre;
        off[i] = o;
        cur[i] = o;
    }
    if (b == 0 && t == 0) off[n] = E;
}

// 4 edges per thread, vectorized src/dst loads.
__global__ void fill_kernel(const int* __restrict__ ei, int* __restrict__ cur,
                            int* __restrict__ csr, int E) {
    int is64 = detect64(ei);
    int e0 = 4 * (blockIdx.x * blockDim.x + threadIdx.x);
    if (e0 >= E) return;
    int s[4], d[4];
    if (e0 + 4 <= E) {
        if (is64) {
            const longlong2* ps = (const longlong2*)ei + e0 / 2;
            const longlong2* pd = (const longlong2*)ei + E / 2 + e0 / 2;
            longlong2 sa = ps[0], sb = ps[1], da = pd[0], db = pd[1];
            s[0] = (int)sa.x; s[1] = (int)sa.y; s[2] = (int)sb.x; s[3] = (int)sb.y;
            d[0] = (int)da.x; d[1] = (int)da.y; d[2] = (int)db.x; d[3] = (int)db.y;
        } else {
            int4 s4 = *(const int4*)(ei + e0);
            int4 d4 = *(const int4*)(ei + E + e0);
            s[0] = s4.x; s[1] = s4.y; s[2] = s4.z; s[3] = s4.w;
            d[0] = d4.x; d[1] = d4.y; d[2] = d4.z; d[3] = d4.w;
        }
#pragma unroll
        for (int k = 0; k < 4; k++) {
            int pos = atomicAdd(&cur[d[k]], 1);
            csr[pos] = s[k];
        }
    } else {
        for (int e = e0; e < E; e++) {
            int ss, dd;
            if (is64) {
                ss = ei[2 * (long long)e];
                dd = ei[2 * ((long long)E + e)];
            } else {
                ss = ei[e];
                dd = ei[(long long)E + e];
            }
            int pos = atomicAdd(&cur[dd], 1);
            csr[pos] = ss;
        }
    }
}

// ---------------------------------------------------------------------------
// Tiled GEMM + row scale: y[i][c] = (sum_k X[i][k] W[k][c]) * dinv[i]
// ---------------------------------------------------------------------------
template <int K>
__global__ __launch_bounds__(256) void gemm_scale_kernel(
    const float* __restrict__ X, const float* __restrict__ W,
    const float* __restrict__ dinv, float* __restrict__ y, int n)
{
    constexpr int BN = 128;
    constexpr int KC = 32;
    __shared__ __align__(16) float Xs[BN][KC];
    __shared__ __align__(16) float Ws[KC][64];

    int tid = threadIdx.x;
    int cg  = tid & 15;
    int ng  = tid >> 4;
    int node0 = blockIdx.x * BN;

    float4 accv[8];
#pragma unroll
    for (int i = 0; i < 8; i++) accv[i] = make_float4(0.f, 0.f, 0.f, 0.f);

    for (int kc = 0; kc < K; kc += KC) {
#pragma unroll
        for (int l = 0; l < 4; l++) {
            int fi = tid + l * 256;
            int r  = fi >> 3;
            int c  = (fi & 7) << 2;
            int node = node0 + r;
            float4 v = make_float4(0.f, 0.f, 0.f, 0.f);
            if (node < n) v = *(const float4*)(X + (size_t)node * K + kc + c);
            *(float4*)(&Xs[r][c]) = v;
        }
#pragma unroll
        for (int l = 0; l < 2; l++) {
            int fi = tid + l * 256;
            int r  = fi >> 4;
            int c  = (fi & 15) << 2;
            *(float4*)(&Ws[r][c]) = *(const float4*)(W + (size_t)(kc + r) * 64 + c);
        }
        __syncthreads();

#pragma unroll
        for (int k4 = 0; k4 < KC; k4 += 4) {
            float4 wr[4];
#pragma unroll
            for (int kk = 0; kk < 4; kk++)
                wr[kk] = *(float4*)(&Ws[k4 + kk][cg << 2]);
#pragma unroll
            for (int i = 0; i < 8; i++) {
                float4 xq = *(float4*)(&Xs[ng + 16 * i][k4]);
                accv[i].x = fmaf(xq.x, wr[0].x, accv[i].x);
                accv[i].y = fmaf(xq.x, wr[0].y, accv[i].y);
                accv[i].z = fmaf(xq.x, wr[0].z, accv[i].z);
                accv[i].w = fmaf(xq.x, wr[0].w, accv[i].w);
                accv[i].x = fmaf(xq.y, wr[1].x, accv[i].x);
                accv[i].y = fmaf(xq.y, wr[1].y, accv[i].y);
                accv[i].z = fmaf(xq.y, wr[1].z, accv[i].z);
                accv[i].w = fmaf(xq.y, wr[1].w, accv[i].w);
                accv[i].x = fmaf(xq.z, wr[2].x, accv[i].x);
                accv[i].y = fmaf(xq.z, wr[2].y, accv[i].y);
                accv[i].z = fmaf(xq.z, wr[2].z, accv[i].z);
                accv[i].w = fmaf(xq.z, wr[2].w, accv[i].w);
                accv[i].x = fmaf(xq.w, wr[3].x, accv[i].x);
                accv[i].y = fmaf(xq.w, wr[3].y, accv[i].y);
                accv[i].z = fmaf(xq.w, wr[3].z, accv[i].z);
                accv[i].w = fmaf(xq.w, wr[3].w, accv[i].w);
            }
        }
        __syncthreads();
    }

#pragma unroll
    for (int i = 0; i < 8; i++) {
        int node = node0 + ng + 16 * i;
        if (node < n) {
            float di = dinv[node];
            float4 v = accv[i];
            v.x *= di; v.y *= di; v.z *= di; v.w *= di;
            *(float4*)(y + (size_t)node * 64 + (cg << 2)) = v;
        }
    }
}

// ---------------------------------------------------------------------------
// Fused gather + epilogue: 16 threads/node, float4/thread, edge loop x4.
// out[d] = (relu)( (y[d] + sum_{j in row d} y[csr[j]]) * dinv[d] + b )
// ---------------------------------------------------------------------------
template <bool RELU>
__global__ __launch_bounds__(256) void gather_kernel(
    const int* __restrict__ off, const int* __restrict__ csr,
    const float4* __restrict__ y, const float* __restrict__ dinv,
    const float4* __restrict__ b, float4* __restrict__ out, int n)
{
    int idx = blockIdx.x * blockDim.x + threadIdx.x;
    int node = idx >> 4;
    if (node >= n) return;
    int c = idx & 15;

    int j   = off[node];
    int end = off[node + 1];

    float4 acc = y[(size_t)node * 16 + c];   // self-loop (pre-scaled)

    for (; j + 4 <= end; j += 4) {
        int s0 = csr[j], s1 = csr[j + 1], s2 = csr[j + 2], s3 = csr[j + 3];
        float4 v0 = y[(size_t)s0 * 16 + c];
        float4 v1 = y[(size_t)s1 * 16 + c];
        float4 v2 = y[(size_t)s2 * 16 + c];
        float4 v3 = y[(size_t)s3 * 16 + c];
        acc.x += (v0.x + v1.x) + (v2.x + v3.x);
        acc.y += (v0.y + v1.y) + (v2.y + v3.y);
        acc.z += (v0.z + v1.z) + (v2.z + v3.z);
        acc.w += (v0.w + v1.w) + (v2.w + v3.w);
    }
    for (; j < end; j++) {
        int s0 = csr[j];
        float4 v0 = y[(size_t)s0 * 16 + c];
        acc.x += v0.x; acc.y += v0.y; acc.z += v0.z; acc.w += v0.w;
    }

    float di = dinv[node];
    float4 bb = b[c];
    float4 r;
    r.x = fmaf(acc.x, di, bb.x);
    r.y = fmaf(acc.y, di, bb.y);
    r.z = fmaf(acc.z, di, bb.z);
    r.w = fmaf(acc.w, di, bb.w);
    if (RELU) {
        r.x = fmaxf(r.x, 0.f);
        r.y = fmaxf(r.y, 0.f);
        r.z = fmaxf(r.z, 0.f);
        r.w = fmaxf(r.w, 0.f);
    }
    out[idx] = r;
}

// ---------------------------------------------------------------------------
extern "C" void kernel_launch(void* const* d_in, const int* in_sizes, int n_in,
                              void* d_out, int out_size)
{
    const float* x  = (const float*)d_in[0];
    const int*   ei = (const int*)d_in[1];
    const float* W1 = (const float*)d_in[2];
    const float* b1 = (const float*)d_in[3];
    const float* W2 = (const float*)d_in[4];
    const float* b2 = (const float*)d_in[5];

    int n = in_sizes[0] / FEAT_IN;   // 100000
    int E = in_sizes[1] / 2;         // 1600000

    float *y, *h, *dinv;
    int *deg, *off, *cur, *csr, *bsum;
    cudaGetSymbolAddress((void**)&y,    g_y);
    cudaGetSymbolAddress((void**)&h,    g_h);
    cudaGetSymbolAddress((void**)&dinv, g_dinv);
    cudaGetSymbolAddress((void**)&deg,  g_deg);
    cudaGetSymbolAddress((void**)&off,  g_off);
    cudaGetSymbolAddress((void**)&cur,  g_cur);
    cudaGetSymbolAddress((void**)&csr,  g_csr);
    cudaGetSymbolAddress((void**)&bsum, g_bsum);

    static cudaStream_t s2 = nullptr;
    static cudaEvent_t evFork = nullptr, evJoin = nullptr;
    if (s2 == nullptr) {
        cudaStreamCreateWithFlags(&s2, cudaStreamNonBlocking);
        cudaEventCreateWithFlags(&evFork, cudaEventDisableTiming);
        cudaEventCreateWithFlags(&evJoin, cudaEventDisableTiming);
    }

    const int T = 256;
    int nb  = (n + T - 1) / T;
    int eb4 = (E / 4 + T - 1) / T;          // 4 edges/thread
    int nbs = (n + 1023) / 1024;            // scan blocks (98)
    int gb  = (n * 16 + T - 1) / T;         // gather blocks

    // ---- Prefix (main stream): deg -> dinv ----
    zero_deg_kernel<<<nb, T>>>(deg, n);
    deg_count_kernel<<<eb4, T>>>(ei, deg, E);
    dinv_kernel<<<nb, T>>>(deg, dinv, n);

    // ---- Fork: scan+fill on s2, GEMM1 on main ----
    cudaEventRecord(evFork, 0);
    cudaStreamWaitEvent(s2, evFork, 0);

    scanA_kernel<<<nbs, 1024, 0, s2>>>(deg, off, bsum, n);
    scanB_kernel<<<nbs, 1024, 0, s2>>>(off, bsum, cur, n, nbs, E);
    fill_kernel<<<eb4, T, 0, s2>>>(ei, cur, csr, E);
    cudaEventRecord(evJoin, s2);

    gemm_scale_kernel<128><<<(n + 127) / 128, 256>>>(x, W1, dinv, y, n);

    // ---- Join ----
    cudaStreamWaitEvent(0, evJoin, 0);

    gather_kernel<true><<<gb, T>>>(off, csr, (const float4*)y, dinv,
                                   (const float4*)b1, (float4*)h, n);

    gemm_scale_kernel<64><<<(n + 127) / 128, 256>>>(h, W2, dinv, y, n);
    gather_kernel<false><<<gb, T>>>(off, csr, (const float4*)y, dinv,
                                    (const float4*)b2, (float4*)d_out, n);
}

// round 5
// speedup vs baseline: 1.1826x; 1.0909x over previous
#include <cuda_runtime.h>
#include <cuda_fp16.h>

// ---------------------------------------------------------------------------
// GCN 2-layer forward, pull-based CSR gather with fp16 aggregation operand:
//   y_h = fp16( (x@W) * dinv[:,None] )               (GEMM fp32 acc + convert)
//   out[d] = ( y[d] + sum_{e:dst=d} y[src_e] ) * dinv[d] + b   (fp32 acc)
// Main stream: deg -> dinv -> GEMM1 -> (join) -> gather1 -> GEMM2 -> gather2
// Side stream: scanA -> scanB -> fill   (overlaps GEMM1)
// ---------------------------------------------------------------------------

#define NODES_MAX 100000
#define EDGES_MAX 1600000
#define FEAT_IN   128
#define FEAT      64

__device__ __half g_y [(size_t)NODES_MAX * FEAT];    // fp16 aggregation operand
__device__ float  g_h [(size_t)NODES_MAX * FEAT];    // layer-1 activations (fp32)
__device__ float  g_dinv[NODES_MAX];
__device__ int    g_deg [NODES_MAX];
__device__ int    g_off [NODES_MAX + 1];
__device__ int    g_cur [NODES_MAX];
__device__ int    g_csr [EDGES_MAX];
__device__ int    g_bsum[256];

// ---------------------------------------------------------------------------
__device__ __forceinline__ int detect64(const int* __restrict__ ei) {
    int lane = threadIdx.x & 31;
    int v = __ldg(&ei[2 * lane + 1]);
    return (__ballot_sync(0xffffffffu, v != 0) == 0u) ? 1 : 0;
}

// 4 edges per thread, vectorized index loads.
__global__ void deg_count_kernel(const int* __restrict__ ei, int* __restrict__ deg, int E) {
    int is64 = detect64(ei);
    int e0 = 4 * (blockIdx.x * blockDim.x + threadIdx.x);
    if (e0 >= E) return;
    if (e0 + 4 <= E) {
        if (is64) {
            const longlong2* p = (const longlong2*)ei + E / 2 + e0 / 2;
            longlong2 a = p[0], b = p[1];
            atomicAdd(&deg[(int)a.x], 1);
            atomicAdd(&deg[(int)a.y], 1);
            atomicAdd(&deg[(int)b.x], 1);
            atomicAdd(&deg[(int)b.y], 1);
        } else {
            int4 d4 = *(const int4*)(ei + E + e0);
            atomicAdd(&deg[d4.x], 1);
            atomicAdd(&deg[d4.y], 1);
            atomicAdd(&deg[d4.z], 1);
            atomicAdd(&deg[d4.w], 1);
        }
    } else {
        for (int e = e0; e < E; e++) {
            long long pos = (long long)E + e;
            int d = is64 ? ei[2 * pos] : ei[pos];
            atomicAdd(&deg[d], 1);
        }
    }
}

__global__ void dinv_kernel(const int* __restrict__ deg, float* __restrict__ dinv, int n) {
    int i = blockIdx.x * blockDim.x + threadIdx.x;
    if (i < n) dinv[i] = rsqrtf((float)(deg[i] + 1));  // +1 self-loop
}

// ---------------------------------------------------------------------------
__device__ __forceinline__ int block_exscan(int v, int* total) {
    __shared__ int wsum[32];
    int lane = threadIdx.x & 31, wid = threadIdx.x >> 5;
    int nw = blockDim.x >> 5;
    int inc = v;
#pragma unroll
    for (int o = 1; o < 32; o <<= 1) {
        int t = __shfl_up_sync(0xffffffffu, inc, o);
        if (lane >= o) inc += t;
    }
    if (lane == 31) wsum[wid] = inc;
    __syncthreads();
    if (wid == 0) {
        int ws = (lane < nw) ? wsum[lane] : 0;
#pragma unroll
        for (int o = 1; o < 32; o <<= 1) {
            int t = __shfl_up_sync(0xffffffffu, ws, o);
            if (lane >= o) ws += t;
        }
        wsum[lane] = ws;
    }
    __syncthreads();
    int woff = (wid == 0) ? 0 : wsum[wid - 1];
    *total = wsum[nw - 1];
    return woff + inc - v;
}

__global__ __launch_bounds__(1024) void scanA_kernel(
    const int* __restrict__ deg, int* __restrict__ off,
    int* __restrict__ bsum, int n)
{
    int i = blockIdx.x * blockDim.x + threadIdx.x;
    int v = (i < n) ? deg[i] : 0;
    int tot;
    int ex = block_exscan(v, &tot);
    if (i < n) off[i] = ex;
    if (threadIdx.x == 0) bsum[blockIdx.x] = tot;
}

__global__ __launch_bounds__(1024) void scanB_kernel(
    int* __restrict__ off, const int* __restrict__ bsum,
    int* __restrict__ cur, int n, int nb, int E)
{
    __shared__ int sb[128];
    int t = threadIdx.x, b = blockIdx.x;
    if (t < 128) sb[t] = (t < nb && t < b) ? bsum[t] : 0;
    __syncthreads();
#pragma unroll
    for (int o = 64; o > 0; o >>= 1) {
        if (t < o) sb[t] += sb[t + o];
        __syncthreads();
    }
    int pre = sb[0];
    int i = b * blockDim.x + t;
    if (i < n) {
        int o = off[i] + pre;
        off[i] = o;
        cur[i] = o;
    }
    if (b == 0 && t == 0) off[n] = E;
}

__global__ void fill_kernel(const int* __restrict__ ei, int* __restrict__ cur,
                            int* __restrict__ csr, int E) {
    int is64 = detect64(ei);
    int e0 = 4 * (blockIdx.x * blockDim.x + threadIdx.x);
    if (e0 >= E) return;
    int s[4], d[4];
    if (e0 + 4 <= E) {
        if (is64) {
            const longlong2* ps = (const longlong2*)ei + e0 / 2;
            const longlong2* pd = (const longlong2*)ei + E / 2 + e0 / 2;
            longlong2 sa = ps[0], sb = ps[1], da = pd[0], db = pd[1];
            s[0] = (int)sa.x; s[1] = (int)sa.y; s[2] = (int)sb.x; s[3] = (int)sb.y;
            d[0] = (int)da.x; d[1] = (int)da.y; d[2] = (int)db.x; d[3] = (int)db.y;
        } else {
            int4 s4 = *(const int4*)(ei + e0);
            int4 d4 = *(const int4*)(ei + E + e0);
            s[0] = s4.x; s[1] = s4.y; s[2] = s4.z; s[3] = s4.w;
            d[0] = d4.x; d[1] = d4.y; d[2] = d4.z; d[3] = d4.w;
        }
#pragma unroll
        for (int k = 0; k < 4; k++) {
            int pos = atomicAdd(&cur[d[k]], 1);
            csr[pos] = s[k];
        }
    } else {
        for (int e = e0; e < E; e++) {
            int ss, dd;
            if (is64) {
                ss = ei[2 * (long long)e];
                dd = ei[2 * ((long long)E + e)];
            } else {
                ss = ei[e];
                dd = ei[(long long)E + e];
            }
            int pos = atomicAdd(&cur[dd], 1);
            csr[pos] = ss;
        }
    }
}

// ---------------------------------------------------------------------------
// Tiled GEMM + row scale + fp16 convert:
//   y_h[i][c] = half( (sum_k X[i][k] W[k][c]) * dinv[i] )
// ---------------------------------------------------------------------------
template <int K>
__global__ __launch_bounds__(256) void gemm_scale_h_kernel(
    const float* __restrict__ X, const float* __restrict__ W,
    const float* __restrict__ dinv, __half* __restrict__ yh, int n)
{
    constexpr int BN = 128;
    constexpr int KC = 32;
    __shared__ __align__(16) float Xs[BN][KC];
    __shared__ __align__(16) float Ws[KC][64];

    int tid = threadIdx.x;
    int cg  = tid & 15;
    int ng  = tid >> 4;
    int node0 = blockIdx.x * BN;

    float4 accv[8];
#pragma unroll
    for (int i = 0; i < 8; i++) accv[i] = make_float4(0.f, 0.f, 0.f, 0.f);

    for (int kc = 0; kc < K; kc += KC) {
#pragma unroll
        for (int l = 0; l < 4; l++) {
            int fi = tid + l * 256;
            int r  = fi >> 3;
            int c  = (fi & 7) << 2;
            int node = node0 + r;
            float4 v = make_float4(0.f, 0.f, 0.f, 0.f);
            if (node < n) v = *(const float4*)(X + (size_t)node * K + kc + c);
            *(float4*)(&Xs[r][c]) = v;
        }
#pragma unroll
        for (int l = 0; l < 2; l++) {
            int fi = tid + l * 256;
            int r  = fi >> 4;
            int c  = (fi & 15) << 2;
            *(float4*)(&Ws[r][c]) = *(const float4*)(W + (size_t)(kc + r) * 64 + c);
        }
        __syncthreads();

#pragma unroll
        for (int k4 = 0; k4 < KC; k4 += 4) {
            float4 wr[4];
#pragma unroll
            for (int kk = 0; kk < 4; kk++)
                wr[kk] = *(float4*)(&Ws[k4 + kk][cg << 2]);
#pragma unroll
            for (int i = 0; i < 8; i++) {
                float4 xq = *(float4*)(&Xs[ng + 16 * i][k4]);
                accv[i].x = fmaf(xq.x, wr[0].x, accv[i].x);
                accv[i].y = fmaf(xq.x, wr[0].y, accv[i].y);
                accv[i].z = fmaf(xq.x, wr[0].z, accv[i].z);
                accv[i].w = fmaf(xq.x, wr[0].w, accv[i].w);
                accv[i].x = fmaf(xq.y, wr[1].x, accv[i].x);
                accv[i].y = fmaf(xq.y, wr[1].y, accv[i].y);
                accv[i].z = fmaf(xq.y, wr[1].z, accv[i].z);
                accv[i].w = fmaf(xq.y, wr[1].w, accv[i].w);
                accv[i].x = fmaf(xq.z, wr[2].x, accv[i].x);
                accv[i].y = fmaf(xq.z, wr[2].y, accv[i].y);
                accv[i].z = fmaf(xq.z, wr[2].z, accv[i].z);
                accv[i].w = fmaf(xq.z, wr[2].w, accv[i].w);
                accv[i].x = fmaf(xq.w, wr[3].x, accv[i].x);
                accv[i].y = fmaf(xq.w, wr[3].y, accv[i].y);
                accv[i].z = fmaf(xq.w, wr[3].z, accv[i].z);
                accv[i].w = fmaf(xq.w, wr[3].w, accv[i].w);
            }
        }
        __syncthreads();
    }

#pragma unroll
    for (int i = 0; i < 8; i++) {
        int node = node0 + ng + 16 * i;
        if (node < n) {
            float di = dinv[node];
            float4 v = accv[i];
            __half2 h0 = __floats2half2_rn(v.x * di, v.y * di);
            __half2 h1 = __floats2half2_rn(v.z * di, v.w * di);
            uint2 u;
            u.x = *reinterpret_cast<unsigned*>(&h0);
            u.y = *reinterpret_cast<unsigned*>(&h1);
            *(uint2*)(yh + (size_t)node * 64 + (cg << 2)) = u;
        }
    }
}

// ---------------------------------------------------------------------------
// Fused gather + epilogue (fp16 rows, fp32 accumulate):
// 16 threads/node, uint2 (4 halves) per thread, edge loop x4.
// ---------------------------------------------------------------------------
__device__ __forceinline__ void acc_h4(float4& acc, uint2 u) {
    float2 a = __half22float2(*reinterpret_cast<__half2*>(&u.x));
    float2 b = __half22float2(*reinterpret_cast<__half2*>(&u.y));
    acc.x += a.x; acc.y += a.y; acc.z += b.x; acc.w += b.y;
}

template <bool RELU>
__global__ __launch_bounds__(256) void gather_kernel(
    const int* __restrict__ off, const int* __restrict__ csr,
    const uint2* __restrict__ yh, const float* __restrict__ dinv,
    const float4* __restrict__ b, float4* __restrict__ out, int n)
{
    int idx = blockIdx.x * blockDim.x + threadIdx.x;
    int node = idx >> 4;
    if (node >= n) return;
    int c = idx & 15;

    int j   = off[node];
    int end = off[node + 1];

    float4 acc = make_float4(0.f, 0.f, 0.f, 0.f);
    acc_h4(acc, yh[(size_t)node * 16 + c]);   // self-loop (pre-scaled)

    for (; j + 4 <= end; j += 4) {
        int s0 = csr[j], s1 = csr[j + 1], s2 = csr[j + 2], s3 = csr[j + 3];
        uint2 v0 = yh[(size_t)s0 * 16 + c];
        uint2 v1 = yh[(size_t)s1 * 16 + c];
        uint2 v2 = yh[(size_t)s2 * 16 + c];
        uint2 v3 = yh[(size_t)s3 * 16 + c];
        acc_h4(acc, v0);
        acc_h4(acc, v1);
        acc_h4(acc, v2);
        acc_h4(acc, v3);
    }
    for (; j < end; j++) {
        uint2 v0 = yh[(size_t)csr[j] * 16 + c];
        acc_h4(acc, v0);
    }

    float di = dinv[node];
    float4 bb = b[c];
    float4 r;
    r.x = fmaf(acc.x, di, bb.x);
    r.y = fmaf(acc.y, di, bb.y);
    r.z = fmaf(acc.z, di, bb.z);
    r.w = fmaf(acc.w, di, bb.w);
    if (RELU) {
        r.x = fmaxf(r.x, 0.f);
        r.y = fmaxf(r.y, 0.f);
        r.z = fmaxf(r.z, 0.f);
        r.w = fmaxf(r.w, 0.f);
    }
    out[idx] = r;
}

// ---------------------------------------------------------------------------
extern "C" void kernel_launch(void* const* d_in, const int* in_sizes, int n_in,
                              void* d_out, int out_size)
{
    const float* x  = (const float*)d_in[0];
    const int*   ei = (const int*)d_in[1];
    const float* W1 = (const float*)d_in[2];
    const float* b1 = (const float*)d_in[3];
    const float* W2 = (const float*)d_in[4];
    const float* b2 = (const float*)d_in[5];

    int n = in_sizes[0] / FEAT_IN;   // 100000
    int E = in_sizes[1] / 2;         // 1600000

    __half* yh;
    float *h, *dinv;
    int *deg, *off, *cur, *csr, *bsum;
    cudaGetSymbolAddress((void**)&yh,   g_y);
    cudaGetSymbolAddress((void**)&h,    g_h);
    cudaGetSymbolAddress((void**)&dinv, g_dinv);
    cudaGetSymbolAddress((void**)&deg,  g_deg);
    cudaGetSymbolAddress((void**)&off,  g_off);
    cudaGetSymbolAddress((void**)&cur,  g_cur);
    cudaGetSymbolAddress((void**)&csr,  g_csr);
    cudaGetSymbolAddress((void**)&bsum, g_bsum);

    static cudaStream_t s2 = nullptr;
    static cudaEvent_t evFork = nullptr, evJoin = nullptr;
    if (s2 == nullptr) {
        cudaStreamCreateWithFlags(&s2, cudaStreamNonBlocking);
        cudaEventCreateWithFlags(&evFork, cudaEventDisableTiming);
        cudaEventCreateWithFlags(&evJoin, cudaEventDisableTiming);
    }

    const int T = 256;
    int nb  = (n + T - 1) / T;
    int eb4 = (E / 4 + T - 1) / T;          // 4 edges/thread
    int nbs = (n + 1023) / 1024;            // scan blocks (98)
    int gb  = (n * 16 + T - 1) / T;         // gather blocks

    // ---- Prefix (main stream): deg -> dinv ----
    cudaMemsetAsync(deg, 0, (size_t)n * sizeof(int), 0);
    deg_count_kernel<<<eb4, T>>>(ei, deg, E);
    dinv_kernel<<<nb, T>>>(deg, dinv, n);

    // ---- Fork: scan+fill on s2, GEMM1 on main ----
    cudaEventRecord(evFork, 0);
    cudaStreamWaitEvent(s2, evFork, 0);

    scanA_kernel<<<nbs, 1024, 0, s2>>>(deg, off, bsum, n);
    scanB_kernel<<<nbs, 1024, 0, s2>>>(off, bsum, cur, n, nbs, E);
    fill_kernel<<<eb4, T, 0, s2>>>(ei, cur, csr, E);
    cudaEventRecord(evJoin, s2);

    gemm_scale_h_kernel<128><<<(n + 127) / 128, 256>>>(x, W1, dinv, yh, n);

    // ---- Join ----
    cudaStreamWaitEvent(0, evJoin, 0);

    gather_kernel<true><<<gb, T>>>(off, csr, (const uint2*)yh, dinv,
                                   (const float4*)b1, (float4*)h, n);

    gemm_scale_h_kernel<64><<<(n + 127) / 128, 256>>>(h, W2, dinv, yh, n);
    gather_kernel<false><<<gb, T>>>(off, csr, (const uint2*)yh, dinv,
                                    (const float4*)b2, (float4*)d_out, n);
}